// round 2
// baseline (speedup 1.0000x reference)
#include <cuda_runtime.h>

#define NN 50000
#define EE 500000
#define SD 128
#define HID 64
#define DEPTH 4
#define CUTF 5.0f
#define PI_F 3.14159265358979f

#define TE 64
#define NT_E ((EE + TE - 1) / TE)
#define TN 64
#define NT_N ((NN + TN - 1) / TN)

// ---------------- device scratch (no allocs allowed) ----------------
__device__ float g_sbuf[NN * SD];
__device__ float g_vbuf[NN * 9];
__device__ float g_sagg[NN * SD];
__device__ float g_vagg[NN * 9];
__device__ float g_C[EE];
__device__ float g_cnt[NN];
__device__ float g_icnt[NN];

__device__ __forceinline__ float silu_f(float x) {
    return x / (1.0f + __expf(-x));
}

// ---------------- small kernels ----------------
__global__ void k_init(const float* __restrict__ s, const float* __restrict__ v) {
    int i = blockIdx.x * blockDim.x + threadIdx.x;
    int stride = gridDim.x * blockDim.x;
    for (int j = i; j < NN * SD; j += stride) g_sbuf[j] = s[j];
    for (int j = i; j < NN * 9; j += stride) g_vbuf[j] = v[j];
    for (int j = i; j < NN; j += stride) g_cnt[j] = 0.0f;
}

__global__ void k_edgepre(const int* __restrict__ ei, const float* __restrict__ d) {
    int e = blockIdx.x * blockDim.x + threadIdx.x;
    if (e < EE) {
        float dd = d[e];
        float c = (dd < CUTF) ? 0.5f * (cosf(PI_F * dd / CUTF) + 1.0f) : 0.0f;
        g_C[e] = c;
        atomicAdd(&g_cnt[ei[e]], 1.0f);
    }
}

__global__ void k_inv() {
    int n = blockIdx.x * blockDim.x + threadIdx.x;
    if (n < NN) g_icnt[n] = 1.0f / fmaxf(g_cnt[n], 1.0f);
}

__global__ void k_zero() {
    int i = blockIdx.x * blockDim.x + threadIdx.x;
    int stride = gridDim.x * blockDim.x;
    for (int j = i; j < NN * SD; j += stride) g_sagg[j] = 0.0f;
    for (int j = i; j < NN * 9; j += stride) g_vagg[j] = 0.0f;
}

__global__ void k_vupd() {
    int i = blockIdx.x * blockDim.x + threadIdx.x;
    if (i < NN * 9) {
        int n = i / 9;
        g_vbuf[i] += g_vagg[i] * g_icnt[n];
    }
}

__global__ void k_out(float* __restrict__ out) {
    int i = blockIdx.x * blockDim.x + threadIdx.x;
    int stride = gridDim.x * blockDim.x;
    for (int j = i; j < NN * SD; j += stride) out[j] = g_sbuf[j];
    for (int j = i; j < NN * 9; j += stride) out[NN * SD + j] = g_vbuf[j];
}

// ---------------- edge kernel ----------------
// shared layout (float offsets)
#define E_W1 0
#define E_B1 (E_W1 + 257 * 64)          // 16448
#define E_W2 (E_B1 + 64)
#define E_B2 (E_W2 + 64 * 64)
#define E_W3 (E_B2 + 64)
#define E_B3 (E_W3 + 64 * 136)
#define E_XT (E_B3 + 136)               // 29512
#define E_H1 (E_XT + 257 * 68)          // 46988
#define E_H2 (E_H1 + 64 * 68)           // 51340
#define E_CS (E_H2 + 64 * 68)           // 55692
#define E_DS (E_CS + 64)
#define E_SS (E_DS + 64)
#define E_TOT (E_SS + 64)               // 55884 floats = 223536 B

__global__ void __launch_bounds__(256, 1) k_edge(
    const int* __restrict__ ei, const float* __restrict__ darr,
    const float* __restrict__ rarr,
    const float* __restrict__ W1, const float* __restrict__ b1,
    const float* __restrict__ W2, const float* __restrict__ b2,
    const float* __restrict__ W3, const float* __restrict__ b3)
{
    extern __shared__ float sm[];
    float* W1s = sm + E_W1;
    float* b1s = sm + E_B1;
    float* W2s = sm + E_W2;
    float* b2s = sm + E_B2;
    float* W3s = sm + E_W3;
    float* b3s = sm + E_B3;
    float* Xt  = sm + E_XT;   // [257][68]
    float* H1  = sm + E_H1;   // [64][68] (out-major)
    float* H2  = sm + E_H2;   // [64][68]
    float* CS  = sm + E_CS;
    int*   dstS = (int*)(sm + E_DS);
    int*   srcS = (int*)(sm + E_SS);

    const int tid = threadIdx.x;

    // load weights into shared once per block
    for (int i = tid; i < 257 * 64; i += 256) W1s[i] = W1[i];
    for (int i = tid; i < 64 * 64; i += 256) W2s[i] = W2[i];
    for (int i = tid; i < 64 * 134; i += 256) {
        int k = i / 134, o = i % 134;
        W3s[k * 136 + o] = W3[i];
    }
    if (tid < 64) { b1s[tid] = b1[tid]; b2s[tid] = b2[tid]; }
    for (int i = tid; i < 134; i += 256) b3s[i] = b3[i];
    __syncthreads();

    const int wid = tid >> 5, lane = tid & 31;

    for (int tile = blockIdx.x; tile < NT_E; tile += gridDim.x) {
        const int base = tile * TE;
        const int nE = min(TE, EE - base);

        // ---- gather X^T [k][e] ----
        for (int ee = wid; ee < TE; ee += 8) {
            const int e = base + ee;
            const bool valid = (ee < nE);
            int dst = 0, src = 0;
            if (valid) { dst = ei[e]; src = ei[EE + e]; }
            const float* sd_ = &g_sbuf[dst * SD];
            const float* ss_ = &g_sbuf[src * SD];
            #pragma unroll
            for (int k4 = 0; k4 < 4; k4++) {
                int k = lane + k4 * 32;
                Xt[k * 68 + ee]        = valid ? sd_[k] : 0.0f;
                Xt[(SD + k) * 68 + ee] = valid ? ss_[k] : 0.0f;
            }
            if (lane == 0) {
                Xt[256 * 68 + ee] = valid ? darr[e] : 0.0f;
                CS[ee] = valid ? g_C[e] : 0.0f;
                dstS[ee] = dst; srcS[ee] = src;
            }
        }
        __syncthreads();

        // ---- GEMM1: [64e x 257] @ [257 x 64] -> silu -> H1 (out-major) ----
        {
            const int ox = (tid & 15) * 4;
            const int ey = (tid >> 4) * 4;
            float acc[4][4];
            #pragma unroll
            for (int j = 0; j < 4; j++) {
                float b = b1s[ox + j];
                acc[0][j] = b; acc[1][j] = b; acc[2][j] = b; acc[3][j] = b;
            }
            #pragma unroll 4
            for (int k = 0; k < 257; k++) {
                float4 w = *(const float4*)(W1s + k * 64 + ox);
                float4 x = *(const float4*)(Xt + k * 68 + ey);
                acc[0][0] += x.x * w.x; acc[0][1] += x.x * w.y; acc[0][2] += x.x * w.z; acc[0][3] += x.x * w.w;
                acc[1][0] += x.y * w.x; acc[1][1] += x.y * w.y; acc[1][2] += x.y * w.z; acc[1][3] += x.y * w.w;
                acc[2][0] += x.z * w.x; acc[2][1] += x.z * w.y; acc[2][2] += x.z * w.z; acc[2][3] += x.z * w.w;
                acc[3][0] += x.w * w.x; acc[3][1] += x.w * w.y; acc[3][2] += x.w * w.z; acc[3][3] += x.w * w.w;
            }
            #pragma unroll
            for (int j = 0; j < 4; j++)
                #pragma unroll
                for (int i = 0; i < 4; i++)
                    H1[(ox + j) * 68 + ey + i] = silu_f(acc[i][j]);
        }
        __syncthreads();

        // ---- GEMM2: [64e x 64] @ [64 x 64] -> silu -> H2 ----
        {
            const int ox = (tid & 15) * 4;
            const int ey = (tid >> 4) * 4;
            float acc[4][4];
            #pragma unroll
            for (int j = 0; j < 4; j++) {
                float b = b2s[ox + j];
                acc[0][j] = b; acc[1][j] = b; acc[2][j] = b; acc[3][j] = b;
            }
            #pragma unroll 4
            for (int k = 0; k < 64; k++) {
                float4 w = *(const float4*)(W2s + k * 64 + ox);
                float4 x = *(const float4*)(H1 + k * 68 + ey);
                acc[0][0] += x.x * w.x; acc[0][1] += x.x * w.y; acc[0][2] += x.x * w.z; acc[0][3] += x.x * w.w;
                acc[1][0] += x.y * w.x; acc[1][1] += x.y * w.y; acc[1][2] += x.y * w.z; acc[1][3] += x.y * w.w;
                acc[2][0] += x.z * w.x; acc[2][1] += x.z * w.y; acc[2][2] += x.z * w.z; acc[2][3] += x.z * w.w;
                acc[3][0] += x.w * w.x; acc[3][1] += x.w * w.y; acc[3][2] += x.w * w.z; acc[3][3] += x.w * w.w;
            }
            #pragma unroll
            for (int j = 0; j < 4; j++)
                #pragma unroll
                for (int i = 0; i < 4; i++)
                    H2[(ox + j) * 68 + ey + i] = silu_f(acc[i][j]);
        }
        __syncthreads();

        // ---- GEMM3 scalar part: [64e x 64] @ [64 x 128], fused scatter ----
        {
            const int ox = (tid & 15) * 8;
            const int ey = (tid >> 4) * 4;
            float acc[4][8];
            #pragma unroll
            for (int j = 0; j < 8; j++) {
                float b = b3s[ox + j];
                acc[0][j] = b; acc[1][j] = b; acc[2][j] = b; acc[3][j] = b;
            }
            #pragma unroll 4
            for (int k = 0; k < 64; k++) {
                float4 wa = *(const float4*)(W3s + k * 136 + ox);
                float4 wb = *(const float4*)(W3s + k * 136 + ox + 4);
                float4 x = *(const float4*)(H2 + k * 68 + ey);
                acc[0][0] += x.x * wa.x; acc[0][1] += x.x * wa.y; acc[0][2] += x.x * wa.z; acc[0][3] += x.x * wa.w;
                acc[0][4] += x.x * wb.x; acc[0][5] += x.x * wb.y; acc[0][6] += x.x * wb.z; acc[0][7] += x.x * wb.w;
                acc[1][0] += x.y * wa.x; acc[1][1] += x.y * wa.y; acc[1][2] += x.y * wa.z; acc[1][3] += x.y * wa.w;
                acc[1][4] += x.y * wb.x; acc[1][5] += x.y * wb.y; acc[1][6] += x.y * wb.z; acc[1][7] += x.y * wb.w;
                acc[2][0] += x.z * wa.x; acc[2][1] += x.z * wa.y; acc[2][2] += x.z * wa.z; acc[2][3] += x.z * wa.w;
                acc[2][4] += x.z * wb.x; acc[2][5] += x.z * wb.y; acc[2][6] += x.z * wb.z; acc[2][7] += x.z * wb.w;
                acc[3][0] += x.w * wa.x; acc[3][1] += x.w * wa.y; acc[3][2] += x.w * wa.z; acc[3][3] += x.w * wa.w;
                acc[3][4] += x.w * wb.x; acc[3][5] += x.w * wb.y; acc[3][6] += x.w * wb.z; acc[3][7] += x.w * wb.w;
            }
            #pragma unroll
            for (int i = 0; i < 4; i++) {
                const int ee = ey + i;
                if (ee < nE) {
                    const float c = CS[ee];
                    float* dp = &g_sagg[dstS[ee] * SD + ox];
                    #pragma unroll
                    for (int j = 0; j < 8; j++) atomicAdd(&dp[j], acc[i][j] * c);
                }
            }
        }

        // ---- GEMM3 vector gates (6 outputs) + vector scatter ----
        if (tid < TE) {
            const int ee = tid;
            if (ee < nE) {
                float a[6];
                #pragma unroll
                for (int j = 0; j < 6; j++) a[j] = b3s[128 + j];
                #pragma unroll 4
                for (int k = 0; k < 64; k++) {
                    float x = H2[k * 68 + ee];
                    #pragma unroll
                    for (int j = 0; j < 6; j++) a[j] += x * W3s[k * 136 + 128 + j];
                }
                const float c = CS[ee];
                const int dst = dstS[ee], src = srcS[ee];
                const int e = base + ee;
                float rv[3];
                #pragma unroll
                for (int x = 0; x < 3; x++) rv[x] = rarr[e * 3 + x];
                #pragma unroll
                for (int vi = 0; vi < 3; vi++) {
                    const float gv = a[vi], gr = a[3 + vi];
                    #pragma unroll
                    for (int x = 0; x < 3; x++) {
                        float val = (g_vbuf[src * 9 + vi * 3 + x] * gv + rv[x] * gr) * c;
                        atomicAdd(&g_vagg[dst * 9 + vi * 3 + x], val);
                    }
                }
            }
        }
        __syncthreads();
    }
}

// ---------------- node kernel ----------------
#define N_W1 0
#define N_B1 (256 * 64)                 // 16384
#define N_W2 (N_B1 + 64)                // 16448
#define N_B2 (N_W2 + 64 * 128)          // 24640
#define N_XT (N_B2 + 128)               // 24768
#define N_UT (N_XT + 256 * 68)          // 42176
#define N_TOT (N_UT + 64 * 68)          // 46528 floats = 186112 B

__global__ void __launch_bounds__(256, 1) k_node(
    const float* __restrict__ Wn1, const float* __restrict__ bn1,
    const float* __restrict__ Wn2, const float* __restrict__ bn2)
{
    extern __shared__ float sm[];
    float* W1s = sm + N_W1;
    float* b1s = sm + N_B1;
    float* W2s = sm + N_W2;
    float* b2s = sm + N_B2;
    float* Xt  = sm + N_XT;   // [256][68]
    float* Ut  = sm + N_UT;   // [64][68]

    const int tid = threadIdx.x;
    for (int i = tid; i < 256 * 64; i += 256) W1s[i] = Wn1[i];
    for (int i = tid; i < 64 * 128; i += 256) W2s[i] = Wn2[i];
    if (tid < 64) b1s[tid] = bn1[tid];
    if (tid < 128) b2s[tid] = bn2[tid];
    __syncthreads();

    const int wid = tid >> 5, lane = tid & 31;

    for (int tile = blockIdx.x; tile < NT_N; tile += gridDim.x) {
        const int base = tile * TN;
        const int nNd = min(TN, NN - base);

        for (int ii = wid; ii < TN; ii += 8) {
            const int n = base + ii;
            const bool valid = (ii < nNd);
            const float* sp = &g_sbuf[(valid ? n : 0) * SD];
            const float* ap = &g_sagg[(valid ? n : 0) * SD];
            #pragma unroll
            for (int k4 = 0; k4 < 4; k4++) {
                int k = lane + k4 * 32;
                Xt[k * 68 + ii]        = valid ? sp[k] : 0.0f;
                Xt[(SD + k) * 68 + ii] = valid ? ap[k] : 0.0f;
            }
        }
        __syncthreads();

        // GEMM1: [64n x 256] @ [256 x 64] -> silu -> Ut
        {
            const int ox = (tid & 15) * 4;
            const int ey = (tid >> 4) * 4;
            float acc[4][4];
            #pragma unroll
            for (int j = 0; j < 4; j++) {
                float b = b1s[ox + j];
                acc[0][j] = b; acc[1][j] = b; acc[2][j] = b; acc[3][j] = b;
            }
            #pragma unroll 4
            for (int k = 0; k < 256; k++) {
                float4 w = *(const float4*)(W1s + k * 64 + ox);
                float4 x = *(const float4*)(Xt + k * 68 + ey);
                acc[0][0] += x.x * w.x; acc[0][1] += x.x * w.y; acc[0][2] += x.x * w.z; acc[0][3] += x.x * w.w;
                acc[1][0] += x.y * w.x; acc[1][1] += x.y * w.y; acc[1][2] += x.y * w.z; acc[1][3] += x.y * w.w;
                acc[2][0] += x.z * w.x; acc[2][1] += x.z * w.y; acc[2][2] += x.z * w.z; acc[2][3] += x.z * w.w;
                acc[3][0] += x.w * w.x; acc[3][1] += x.w * w.y; acc[3][2] += x.w * w.z; acc[3][3] += x.w * w.w;
            }
            #pragma unroll
            for (int j = 0; j < 4; j++)
                #pragma unroll
                for (int i = 0; i < 4; i++)
                    Ut[(ox + j) * 68 + ey + i] = silu_f(acc[i][j]);
        }
        __syncthreads();

        // GEMM2: [64n x 64] @ [64 x 128] -> s += .
        {
            const int ox = (tid & 15) * 8;
            const int ey = (tid >> 4) * 4;
            float acc[4][8];
            #pragma unroll
            for (int j = 0; j < 8; j++) {
                float b = b2s[ox + j];
                acc[0][j] = b; acc[1][j] = b; acc[2][j] = b; acc[3][j] = b;
            }
            #pragma unroll 4
            for (int k = 0; k < 64; k++) {
                float4 wa = *(const float4*)(W2s + k * 128 + ox);
                float4 wb = *(const float4*)(W2s + k * 128 + ox + 4);
                float4 x = *(const float4*)(Ut + k * 68 + ey);
                acc[0][0] += x.x * wa.x; acc[0][1] += x.x * wa.y; acc[0][2] += x.x * wa.z; acc[0][3] += x.x * wa.w;
                acc[0][4] += x.x * wb.x; acc[0][5] += x.x * wb.y; acc[0][6] += x.x * wb.z; acc[0][7] += x.x * wb.w;
                acc[1][0] += x.y * wa.x; acc[1][1] += x.y * wa.y; acc[1][2] += x.y * wa.z; acc[1][3] += x.y * wa.w;
                acc[1][4] += x.y * wb.x; acc[1][5] += x.y * wb.y; acc[1][6] += x.y * wb.z; acc[1][7] += x.y * wb.w;
                acc[2][0] += x.z * wa.x; acc[2][1] += x.z * wa.y; acc[2][2] += x.z * wa.z; acc[2][3] += x.z * wa.w;
                acc[2][4] += x.z * wb.x; acc[2][5] += x.z * wb.y; acc[2][6] += x.z * wb.z; acc[2][7] += x.z * wb.w;
                acc[3][0] += x.w * wa.x; acc[3][1] += x.w * wa.y; acc[3][2] += x.w * wa.z; acc[3][3] += x.w * wa.w;
                acc[3][4] += x.w * wb.x; acc[3][5] += x.w * wb.y; acc[3][6] += x.w * wb.z; acc[3][7] += x.w * wb.w;
            }
            #pragma unroll
            for (int i = 0; i < 4; i++) {
                const int n = base + ey + i;
                if (ey + i < nNd) {
                    float* sp = &g_sbuf[n * SD + ox];
                    #pragma unroll
                    for (int j = 0; j < 8; j++) sp[j] += acc[i][j];
                }
            }
        }
        __syncthreads();
    }
}

// ---------------- host launch ----------------
extern "C" void kernel_launch(void* const* d_in, const int* in_sizes, int n_in,
                              void* d_out, int out_size) {
    const float* s   = (const float*)d_in[0];
    const float* v   = (const float*)d_in[1];
    const int*   ei  = (const int*)d_in[2];
    const float* d   = (const float*)d_in[3];
    const float* r   = (const float*)d_in[4];
    const float* W1  = (const float*)d_in[5];
    const float* b1  = (const float*)d_in[6];
    const float* W2  = (const float*)d_in[7];
    const float* b2  = (const float*)d_in[8];
    const float* W3  = (const float*)d_in[9];
    const float* b3  = (const float*)d_in[10];
    const float* Wn1 = (const float*)d_in[11];
    const float* bn1 = (const float*)d_in[12];
    const float* Wn2 = (const float*)d_in[13];
    const float* bn2 = (const float*)d_in[14];
    float* out = (float*)d_out;

    const int esm = E_TOT * 4;
    const int nsm = N_TOT * 4;
    cudaFuncSetAttribute(k_edge, cudaFuncAttributeMaxDynamicSharedMemorySize, esm);
    cudaFuncSetAttribute(k_node, cudaFuncAttributeMaxDynamicSharedMemorySize, nsm);

    k_init<<<1024, 256>>>(s, v);
    k_edgepre<<<(EE + 255) / 256, 256>>>(ei, d);
    k_inv<<<(NN + 255) / 256, 256>>>();

    for (int l = 0; l < DEPTH; l++) {
        k_zero<<<1024, 256>>>();
        k_edge<<<152, 256, esm>>>(ei, d, r,
                                  W1 + l * 257 * 64, b1 + l * 64,
                                  W2 + l * 64 * 64, b2 + l * 64,
                                  W3 + l * 64 * 134, b3 + l * 134);
        k_node<<<152, 256, nsm>>>(Wn1 + l * 256 * 64, bn1 + l * 64,
                                  Wn2 + l * 64 * 128, bn2 + l * 128);
        k_vupd<<<(NN * 9 + 255) / 256, 256>>>();
    }
    k_out<<<1024, 256>>>(out);
}